// round 4
// baseline (speedup 1.0000x reference)
#include <cuda_runtime.h>

// Shapes (fixed by the problem): inputs [L,B,C,H,W] fp32, W [C,C] fp32
#define DL 4
#define DB 8
#define DC 256
#define DHW 4096            // 64*64
#define LBC (DL*DB*DC)      // 8192
#define VEC_PER_LBC 1024    // 4096/4 float4 per (l,b,c) row
#define CHB 2               // batches per chunk
#define NCHUNK (DB / CHB)   // 4

__device__ float g_gap[LBC];

// ---------------------------------------------------------------------------
// G_k: global average pool for chunk k (batches b0, b0+1, all l, all c).
// 1024 blocks; each block reduces TWO consecutive global rows (32KB
// contiguous), 8 front-batched float4 loads per thread. Default cache policy:
// fills L2 (evict-normal) for the immediately following M_k.
// ---------------------------------------------------------------------------
__global__ void __launch_bounds__(256) gap_chunk(const float* __restrict__ in, int b0) {
    const int p = blockIdx.x;                // 0..1023
    const int l  = p >> 8;                   // 0..3
    const int bi = (p >> 7) & 1;             // 0..1
    const int c  = (2 * p) & 255;            // even c
    const int g0 = (l * DB + b0 + bi) * DC + c;   // first of two global rows

    const float4* base = reinterpret_cast<const float4*>(in) + (size_t)g0 * VEC_PER_LBC;
    const int t = threadIdx.x;

    float4 v[8];
#pragma unroll
    for (int i = 0; i < 8; ++i) v[i] = base[i * 256 + t];   // 32KB contiguous, MLP=8

    float s0 = 0.f, s1 = 0.f;
#pragma unroll
    for (int i = 0; i < 4; ++i) s0 += (v[i].x + v[i].y) + (v[i].z + v[i].w);
#pragma unroll
    for (int i = 4; i < 8; ++i) s1 += (v[i].x + v[i].y) + (v[i].z + v[i].w);

#pragma unroll
    for (int o = 16; o > 0; o >>= 1) {
        s0 += __shfl_xor_sync(0xffffffffu, s0, o);
        s1 += __shfl_xor_sync(0xffffffffu, s1, o);
    }

    __shared__ float ws[8][2];
    if ((t & 31) == 0) { ws[t >> 5][0] = s0; ws[t >> 5][1] = s1; }
    __syncthreads();
    if (t == 0) {
        float a = 0.f, b = 0.f;
#pragma unroll
        for (int w = 0; w < 8; ++w) { a += ws[w][0]; b += ws[w][1]; }
        g_gap[g0 + 0] = a * (1.0f / (float)DHW);
        g_gap[g0 + 1] = b * (1.0f / (float)DHW);
    }
}

// ---------------------------------------------------------------------------
// M_k: fused attention + multiply for chunk k. One block per (l, b in chunk,
// c) row (2048 blocks). Front-batch the 4 input float4 loads (L2-hot from
// G_k, __ldcs: no reuse after), compute the 4 scores for (b, d=c) via block
// reduction over input channels, softmax over l, multiply, stream out __stcs.
// ---------------------------------------------------------------------------
__global__ void __launch_bounds__(256) fused_mul_chunk(const float* __restrict__ in,
                                                       const float* __restrict__ Wm,
                                                       float* __restrict__ out, int b0) {
    const int w = blockIdx.x;                // 0..2047 within-chunk row
    const int l0 = w >> 9;                   // 0..3
    const int bi = (w >> 8) & 1;
    const int d  = w & 255;
    const int b  = b0 + bi;
    const int g  = (l0 * DB + b) * DC + d;   // global row
    const int t  = threadIdx.x;

    const size_t base = (size_t)g * VEC_PER_LBC;
    const float4* p = reinterpret_cast<const float4*>(in) + base;
    float4* q = reinterpret_cast<float4*>(out) + base;

    // 1) front-batch the reads (should be L2 hits; evict-first after use)
    float4 v[4];
#pragma unroll
    for (int i = 0; i < 4; ++i) v[i] = __ldcs(&p[i * 256 + t]);

    // 2) attention scores: thread t owns input-channel c=t
    const float wv = __ldg(&Wm[d * DC + t]);
    float part[DL];
#pragma unroll
    for (int l = 0; l < DL; ++l) part[l] = wv * g_gap[(l * DB + b) * DC + t];

#pragma unroll
    for (int o = 16; o > 0; o >>= 1)
#pragma unroll
        for (int l = 0; l < DL; ++l) part[l] += __shfl_xor_sync(0xffffffffu, part[l], o);

    __shared__ float sred[8][DL];
    if ((t & 31) == 0) {
#pragma unroll
        for (int l = 0; l < DL; ++l) sred[t >> 5][l] = part[l];
    }
    __syncthreads();

    float sc[DL];
#pragma unroll
    for (int l = 0; l < DL; ++l) {
        float s = 0.f;
#pragma unroll
        for (int w8 = 0; w8 < 8; ++w8) s += sred[w8][l];
        sc[l] = s;
    }

    // 3) softmax over L, select this block's level
    float m = sc[0];
#pragma unroll
    for (int l = 1; l < DL; ++l) m = fmaxf(m, sc[l]);
    float sum = 0.f, el0 = 0.f;
#pragma unroll
    for (int l = 0; l < DL; ++l) {
        float e = __expf(sc[l] - m);
        sum += e;
        if (l == l0) el0 = e;
    }
    const float a = el0 / sum;

    // 4) multiply + stream out (evict-first stores)
#pragma unroll
    for (int i = 0; i < 4; ++i) {
        v[i].x *= a; v[i].y *= a; v[i].z *= a; v[i].w *= a;
        __stcs(&q[i * 256 + t], v[i]);
    }
}

// ---------------------------------------------------------------------------
extern "C" void kernel_launch(void* const* d_in, const int* in_sizes, int n_in,
                              void* d_out, int out_size) {
    const float* in = (const float*)d_in[0];   // [L,B,C,H,W]
    const float* Wm = (const float*)d_in[1];   // [C,C]
    float* out = (float*)d_out;

    for (int k = 0; k < NCHUNK; ++k) {
        const int b0 = k * CHB;
        gap_chunk<<<(DL * CHB * DC) / 2, 256>>>(in, b0);
        fused_mul_chunk<<<DL * CHB * DC, 256>>>(in, Wm, out, b0);
    }
}

// round 5
// speedup vs baseline: 1.1655x; 1.1655x over previous
#include <cuda_runtime.h>

// Shapes (fixed by the problem): inputs [L,B,C,H,W] fp32, W [C,C] fp32
#define DL 4
#define DB 8
#define DC 256
#define DHW 4096            // 64*64
#define LBC (DL*DB*DC)      // 8192
#define VEC_PER_LBC 1024    // 4096/4 float4 per (l,b,c) row
#define CHB 4               // batches per chunk (67 MB < L2)
#define CH_ROWS (DL*CHB*DC) // 4096 rows per chunk
#define G_BLOCKS (CH_ROWS/2)   // 2048 (2 rows per G block)
#define M_BLOCKS (CH_ROWS)     // 4096 (1 row per M block)

__device__ float g_gap[LBC];

// ---------------------------------------------------------------------------
// G role: average-pool two consecutive global rows (32KB contiguous),
// 8 front-batched float4 loads (MLP=8). Default cache policy: fills L2
// so the following M pass re-reads as hits.
// ---------------------------------------------------------------------------
__device__ __forceinline__ void gap_role(const float* __restrict__ in, int b0, int p) {
    // p in [0, G_BLOCKS): rows 2p, 2p+1 of the chunk
    const int w0 = 2 * p;
    const int l  = w0 >> 10;
    const int bi = (w0 >> 8) & (CHB - 1);
    const int c  = w0 & 255;                       // even
    const int g0 = (l * DB + b0 + bi) * DC + c;

    const float4* base = reinterpret_cast<const float4*>(in) + (size_t)g0 * VEC_PER_LBC;
    const int t = threadIdx.x;

    float4 v[8];
#pragma unroll
    for (int i = 0; i < 8; ++i) v[i] = base[i * 256 + t];

    float s0 = 0.f, s1 = 0.f;
#pragma unroll
    for (int i = 0; i < 4; ++i) s0 += (v[i].x + v[i].y) + (v[i].z + v[i].w);
#pragma unroll
    for (int i = 4; i < 8; ++i) s1 += (v[i].x + v[i].y) + (v[i].z + v[i].w);

#pragma unroll
    for (int o = 16; o > 0; o >>= 1) {
        s0 += __shfl_xor_sync(0xffffffffu, s0, o);
        s1 += __shfl_xor_sync(0xffffffffu, s1, o);
    }

    __shared__ float ws[8][2];
    if ((t & 31) == 0) { ws[t >> 5][0] = s0; ws[t >> 5][1] = s1; }
    __syncthreads();
    if (t == 0) {
        float a = 0.f, b = 0.f;
#pragma unroll
        for (int w = 0; w < 8; ++w) { a += ws[w][0]; b += ws[w][1]; }
        g_gap[g0 + 0] = a * (1.0f / (float)DHW);
        g_gap[g0 + 1] = b * (1.0f / (float)DHW);
    }
}

// ---------------------------------------------------------------------------
// M role: fused attention + multiply for one chunk row. Front-batch the 4
// input float4 loads (L2-hot, __ldcs), compute 4 scores via block reduction,
// softmax over L, multiply, stream out with __stcs.
// ---------------------------------------------------------------------------
__device__ __forceinline__ void mul_role(const float* __restrict__ in,
                                         const float* __restrict__ Wm,
                                         float* __restrict__ out, int b0, int w) {
    const int l0 = w >> 10;
    const int bi = (w >> 8) & (CHB - 1);
    const int d  = w & 255;
    const int b  = b0 + bi;
    const int g  = (l0 * DB + b) * DC + d;
    const int t  = threadIdx.x;

    const size_t base = (size_t)g * VEC_PER_LBC;
    const float4* p = reinterpret_cast<const float4*>(in) + base;
    float4* q = reinterpret_cast<float4*>(out) + base;

    float4 v[4];
#pragma unroll
    for (int i = 0; i < 4; ++i) v[i] = __ldcs(&p[i * 256 + t]);

    const float wv = __ldg(&Wm[d * DC + t]);
    float part[DL];
#pragma unroll
    for (int l = 0; l < DL; ++l) part[l] = wv * g_gap[(l * DB + b) * DC + t];

#pragma unroll
    for (int o = 16; o > 0; o >>= 1)
#pragma unroll
        for (int l = 0; l < DL; ++l) part[l] += __shfl_xor_sync(0xffffffffu, part[l], o);

    __shared__ float sred[8][DL];
    if ((t & 31) == 0) {
#pragma unroll
        for (int l = 0; l < DL; ++l) sred[t >> 5][l] = part[l];
    }
    __syncthreads();

    float sc[DL];
#pragma unroll
    for (int l = 0; l < DL; ++l) {
        float s = 0.f;
#pragma unroll
        for (int w8 = 0; w8 < 8; ++w8) s += sred[w8][l];
        sc[l] = s;
    }

    float m = sc[0];
#pragma unroll
    for (int l = 1; l < DL; ++l) m = fmaxf(m, sc[l]);
    float sum = 0.f, el0 = 0.f;
#pragma unroll
    for (int l = 0; l < DL; ++l) {
        float e = __expf(sc[l] - m);
        sum += e;
        if (l == l0) el0 = e;
    }
    const float a = el0 / sum;

#pragma unroll
    for (int i = 0; i < 4; ++i) {
        v[i].x *= a; v[i].y *= a; v[i].z *= a; v[i].w *= a;
        __stcs(&q[i * 256 + t], v[i]);
    }
}

// ---------------------------------------------------------------------------
// Launch 0: G only (chunk starting at b0).
__global__ void __launch_bounds__(256) g_kernel(const float* __restrict__ in, int b0) {
    gap_role(in, b0, blockIdx.x);
}

// Launch 1: combo — 2:1 interleave of M(b0_m) and G(b0_g). grid = 6144.
// idx%3==2 -> G block (q-th), else M block (2q + r).
__global__ void __launch_bounds__(256) combo_kernel(const float* __restrict__ in,
                                                    const float* __restrict__ Wm,
                                                    float* __restrict__ out,
                                                    int b0_m, int b0_g) {
    const int idx = blockIdx.x;
    const int q = idx / 3;
    const int r = idx - 3 * q;
    if (r == 2) gap_role(in, b0_g, q);
    else        mul_role(in, Wm, out, b0_m, 2 * q + r);
}

// Launch 2: M only (chunk starting at b0). grid = 4096.
__global__ void __launch_bounds__(256) m_kernel(const float* __restrict__ in,
                                                const float* __restrict__ Wm,
                                                float* __restrict__ out, int b0) {
    mul_role(in, Wm, out, b0, blockIdx.x);
}

// ---------------------------------------------------------------------------
extern "C" void kernel_launch(void* const* d_in, const int* in_sizes, int n_in,
                              void* d_out, int out_size) {
    const float* in = (const float*)d_in[0];   // [L,B,C,H,W]
    const float* Wm = (const float*)d_in[1];   // [C,C]
    float* out = (float*)d_out;

    g_kernel<<<G_BLOCKS, 256>>>(in, 0);                         // G(chunk0)
    combo_kernel<<<M_BLOCKS + G_BLOCKS, 256>>>(in, Wm, out, 0, CHB); // M(0) + G(1)
    m_kernel<<<M_BLOCKS, 256>>>(in, Wm, out, CHB);              // M(chunk1)
}